// round 3
// baseline (speedup 1.0000x reference)
#include <cuda_runtime.h>
#include <math.h>
#include <stdint.h>

// ---------------------------------------------------------------------------
// ChildSumTreeLSTM on a perfect binary tree, N = 131071 = 2^17 - 1.
//
// Decomposition:
//   Y[N,1024]  = X @ [W_ioux; W_fx]^T + [b_ioux+b_iouh ; b_fx+b_fh]   (once)
//   leaves:      c = sig(i)*tanh(u), h = sig(o)*tanh(c)   from Y rows
//   per level (bottom-up):
//     G[2c,1024] = h_children @ [W_iouh; W_fh]^T          (children rows are
//                                                          contiguous in h)
//     combine:  iou = Y[n,0:768] + G[l,0:768] + G[r,0:768]
//               f_k = sigmoid(G[k,768:1024] + Y[n,768:1024])
//               c_n = sig(i)*tanh(u) + f_l*c_l + f_r*c_r
//               h_n = sig(o)*tanh(c_n)
// All fp32.
// ---------------------------------------------------------------------------

#define NN 131071

// scratch (device globals; no allocations allowed)
static __device__ float g_Y[(size_t)131072 * 1024];  // packed [ioub | fxb]
static __device__ float g_G[(size_t)65536 * 1024];   // per-level child GEMM out
static __device__ float g_h[(size_t)131072 * 256];
static __device__ float g_c[(size_t)131072 * 256];
static __device__ float g_W1[1024 * 256];            // [W_ioux; W_fx]
static __device__ float g_W2[1024 * 256];            // [W_iouh; W_fh]
static __device__ float g_b1[1024];                  // folded biases

__device__ __forceinline__ float sigmoidf_(float x) {
    return 1.0f / (1.0f + expf(-x));
}

// ---------------------------------------------------------------------------
__global__ void pack_weights_kernel(const float* __restrict__ W_ioux,
                                    const float* __restrict__ b_ioux,
                                    const float* __restrict__ W_iouh,
                                    const float* __restrict__ b_iouh,
                                    const float* __restrict__ W_fx,
                                    const float* __restrict__ b_fx,
                                    const float* __restrict__ W_fh,
                                    const float* __restrict__ b_fh) {
    int i = blockIdx.x * blockDim.x + threadIdx.x;
    if (i >= 1024 * 256) return;
    int r = i >> 8;
    int c = i & 255;
    g_W1[i] = (r < 768) ? W_ioux[i] : W_fx[(r - 768) * 256 + c];
    g_W2[i] = (r < 768) ? W_iouh[i] : W_fh[(r - 768) * 256 + c];
    if (c == 0)
        g_b1[r] = (r < 768) ? (b_ioux[r] + b_iouh[r])
                            : (b_fx[r - 768] + b_fh[r - 768]);
}

// ---------------------------------------------------------------------------
// C[M,1024] = A[M,256] @ B[1024,256]^T (+ bias)
// 64x64 block tile, K-chunk 16, 256 threads, 4x4 register microtile.
__device__ __forceinline__ void gemm_body(const float* __restrict__ A,
                                          const float* __restrict__ B,
                                          const float* __restrict__ bias,
                                          float* __restrict__ C, int M) {
    __shared__ float As[16][68];  // [k][m], stride 68 keeps float4 alignment
    __shared__ float Bs[16][68];  // [k][n]

    const int bm = blockIdx.x * 64;
    const int bn = blockIdx.y * 64;
    const int tid = (int)threadIdx.x;
    const int tx = tid & 15;
    const int ty = tid >> 4;
    const int lr = tid >> 2;        // 0..63: tile row loaded by this thread
    const int lk = (tid & 3) << 2;  // 0,4,8,12: k offset

    float acc[4][4];
#pragma unroll
    for (int i = 0; i < 4; i++)
#pragma unroll
        for (int j = 0; j < 4; j++) acc[i][j] = 0.0f;

    for (int k0 = 0; k0 < 256; k0 += 16) {
        float4 av = make_float4(0.f, 0.f, 0.f, 0.f);
        const int am = bm + lr;
        if (am < M)
            av = *reinterpret_cast<const float4*>(A + (size_t)am * 256 + k0 + lk);
        As[lk + 0][lr] = av.x;
        As[lk + 1][lr] = av.y;
        As[lk + 2][lr] = av.z;
        As[lk + 3][lr] = av.w;

        const float4 bv =
            *reinterpret_cast<const float4*>(B + (size_t)(bn + lr) * 256 + k0 + lk);
        Bs[lk + 0][lr] = bv.x;
        Bs[lk + 1][lr] = bv.y;
        Bs[lk + 2][lr] = bv.z;
        Bs[lk + 3][lr] = bv.w;

        __syncthreads();

#pragma unroll
        for (int k = 0; k < 16; k++) {
            const float4 a = *reinterpret_cast<const float4*>(&As[k][ty << 2]);
            const float4 b = *reinterpret_cast<const float4*>(&Bs[k][tx << 2]);
            acc[0][0] += a.x * b.x; acc[0][1] += a.x * b.y;
            acc[0][2] += a.x * b.z; acc[0][3] += a.x * b.w;
            acc[1][0] += a.y * b.x; acc[1][1] += a.y * b.y;
            acc[1][2] += a.y * b.z; acc[1][3] += a.y * b.w;
            acc[2][0] += a.z * b.x; acc[2][1] += a.z * b.y;
            acc[2][2] += a.z * b.z; acc[2][3] += a.z * b.w;
            acc[3][0] += a.w * b.x; acc[3][1] += a.w * b.y;
            acc[3][2] += a.w * b.z; acc[3][3] += a.w * b.w;
        }
        __syncthreads();
    }

#pragma unroll
    for (int i = 0; i < 4; i++) {
        const int row = bm + (ty << 2) + i;
        if (row >= M) continue;
#pragma unroll
        for (int j = 0; j < 4; j++) {
            const int col = bn + (tx << 2) + j;
            float v = acc[i][j];
            if (bias) v += bias[col];
            C[(size_t)row * 1024 + col] = v;
        }
    }
}

__global__ void gemm_init_kernel(const float* __restrict__ X, int M) {
    gemm_body(X, g_W1, g_b1, g_Y, M);
}

__global__ void gemm_rec_kernel(int cs, int rows) {
    gemm_body(g_h + (size_t)cs * 256, g_W2, nullptr, g_G, rows);
}

// ---------------------------------------------------------------------------
__global__ void leaf_kernel(int start) {
    const int n = start + blockIdx.x;
    const int d = (int)threadIdx.x;
    const float* Yn = g_Y + (size_t)n * 1024;
    const float cv = sigmoidf_(Yn[d]) * tanhf(Yn[512 + d]);
    const float hv = sigmoidf_(Yn[256 + d]) * tanhf(cv);
    g_c[(size_t)n * 256 + d] = cv;
    g_h[(size_t)n * 256 + d] = hv;
}

__global__ void combine_kernel(int start, int cs) {
    const int j = (int)blockIdx.x;   // node index within level
    const int d = (int)threadIdx.x;  // 0..255
    const int n = start + j;
    const float* Yn = g_Y + (size_t)n * 1024;
    const float* Gl = g_G + (size_t)(2 * j) * 1024;
    const float* Gr = g_G + (size_t)(2 * j + 1) * 1024;

    const float iv = Yn[d] + Gl[d] + Gr[d];
    const float ov = Yn[256 + d] + Gl[256 + d] + Gr[256 + d];
    const float uv = Yn[512 + d] + Gl[512 + d] + Gr[512 + d];
    const float fxv = Yn[768 + d];
    const float fl = sigmoidf_(Gl[768 + d] + fxv);
    const float fr = sigmoidf_(Gr[768 + d] + fxv);
    const float cl = g_c[(size_t)(cs + 2 * j) * 256 + d];
    const float cr = g_c[(size_t)(cs + 2 * j + 1) * 256 + d];

    const float cv = sigmoidf_(iv) * tanhf(uv) + fl * cl + fr * cr;
    const float hv = sigmoidf_(ov) * tanhf(cv);
    g_c[(size_t)n * 256 + d] = cv;
    g_h[(size_t)n * 256 + d] = hv;
}

__global__ void write_out_kernel(float* __restrict__ out) {
    const int d = (int)threadIdx.x;  // 0..255
    out[d] = g_c[d];                 // c[0]
    out[256 + d] = g_h[d];           // h[0]
}

// ---------------------------------------------------------------------------
extern "C" void kernel_launch(void* const* d_in, const int* in_sizes, int n_in,
                              void* d_out, int out_size) {
    const float* X      = (const float*)d_in[0];
    const float* W_ioux = (const float*)d_in[1];
    const float* b_ioux = (const float*)d_in[2];
    const float* W_iouh = (const float*)d_in[3];
    const float* b_iouh = (const float*)d_in[4];
    const float* W_fx   = (const float*)d_in[5];
    const float* b_fx   = (const float*)d_in[6];
    const float* W_fh   = (const float*)d_in[7];
    const float* b_fh   = (const float*)d_in[8];
    float* out = (float*)d_out;

    // pack weights + folded biases
    pack_weights_kernel<<<(1024 * 256 + 255) / 256, 256>>>(
        W_ioux, b_ioux, W_iouh, b_iouh, W_fx, b_fx, W_fh, b_fh);

    // Y = X @ W1^T + b1   (M = 131071, N = 1024, K = 256)
    gemm_init_kernel<<<dim3((NN + 63) / 64, 16), 256>>>(X, NN);

    // leaves: level 16, start 65535, count 65536
    leaf_kernel<<<65536, 256>>>(65535);

    // internal levels bottom-up
    for (int lvl = 15; lvl >= 0; lvl--) {
        const int count = 1 << lvl;
        const int start = count - 1;
        const int cs = 2 * start + 1;
        const int rows = 2 * count;
        gemm_rec_kernel<<<dim3((rows + 63) / 64, 16), 256>>>(cs, rows);
        combine_kernel<<<count, 256>>>(start, cs);
    }

    write_out_kernel<<<1, 256>>>(out);
}

// round 5
// speedup vs baseline: 1.2153x; 1.2153x over previous
#include <cuda_runtime.h>
#include <cuda_bf16.h>
#include <math.h>
#include <stdint.h>

// ---------------------------------------------------------------------------
// ChildSumTreeLSTM, perfect binary tree N = 131071 = 2^17 - 1, dims 256/256.
//
//   Y[N,1024]  = X @ [W_ioux; W_fx]^T + folded biases        (HMMA)
//   leaves:      c = sig(i)*tanh(u), h = sig(o)*tanh(c)
//   per level:   G[2c,1024] = h_children @ [W_iouh; W_fh]^T  (HMMA)
//                combine -> c,h of parents
//
// GEMMs on tensor cores via mma.sync.m16n8k16 (bf16 -> fp32) with fp32 split:
//   A*B ~= Ah*Bh + Ah*Bl + Al*Bh
// (tcgen05 is unavailable: harness compiles PTX at target sm_103, not sm_103a)
// ---------------------------------------------------------------------------

#define NN 131071

// ---------------- device scratch (no allocations allowed) ------------------
static __device__ float         g_Y[(size_t)131072 * 1024];
static __device__ float         g_G[(size_t)65536 * 1024];
static __device__ float         g_c[(size_t)131072 * 256];
static __device__ float         g_h[(size_t)131072 * 256];
static __device__ __nv_bfloat16 g_W1h[1024 * 256];
static __device__ __nv_bfloat16 g_W1l[1024 * 256];
static __device__ __nv_bfloat16 g_W2h[1024 * 256];
static __device__ __nv_bfloat16 g_W2l[1024 * 256];
static __device__ float         g_b1[1024];

// ---------------- helpers ---------------------------------------------------
__device__ __forceinline__ float sigmoidf_(float x) { return 1.0f / (1.0f + expf(-x)); }

__device__ __forceinline__ uint32_t smem_u32(const void* p) {
    uint32_t a;
    asm("{ .reg .u64 t; cvta.to.shared.u64 t, %1; cvt.u32.u64 %0, t; }"
        : "=r"(a) : "l"(p));
    return a;
}

__device__ __forceinline__ uint32_t pack_bf16x2(float f0, float f1) {
    const uint16_t u0 = __bfloat16_as_ushort(__float2bfloat16_rn(f0));
    const uint16_t u1 = __bfloat16_as_ushort(__float2bfloat16_rn(f1));
    return (uint32_t)u0 | ((uint32_t)u1 << 16);
}

__device__ __forceinline__ void ldmatrix_x4(uint32_t* r, uint32_t addr) {
    asm volatile("ldmatrix.sync.aligned.m8n8.x4.shared.b16 {%0,%1,%2,%3}, [%4];"
                 : "=r"(r[0]), "=r"(r[1]), "=r"(r[2]), "=r"(r[3]) : "r"(addr));
}

__device__ __forceinline__ void mma16816(float* d, const uint32_t* a,
                                         uint32_t b0, uint32_t b1) {
    asm volatile(
        "mma.sync.aligned.m16n8k16.row.col.f32.bf16.bf16.f32 "
        "{%0,%1,%2,%3}, {%4,%5,%6,%7}, {%8,%9}, {%0,%1,%2,%3};"
        : "+f"(d[0]), "+f"(d[1]), "+f"(d[2]), "+f"(d[3])
        : "r"(a[0]), "r"(a[1]), "r"(a[2]), "r"(a[3]), "r"(b0), "r"(b1));
}

// ---------------- smem layout (padded rows, stride 144 B = 72 bf16) ---------
#define SSTRIDE 144
#define OFF_AH  0
#define OFF_AL  18432
#define OFF_BH  36864
#define OFF_BL  55296
#define SMEM_BYTES 73728

// ---------------------------------------------------------------------------
// C[Mlim,1024] = A[fp32, M x 256] @ B[1024 x 256]^T (+ bias), split-bf16 HMMA.
// Tile 128(m) x 128(n), K chunked by 64, 8 warps each 64x32.
__device__ __forceinline__ void gemm_body(const float* __restrict__ A,
                                          const __nv_bfloat16* __restrict__ Bh,
                                          const __nv_bfloat16* __restrict__ Bl,
                                          float* __restrict__ C, int Mlim,
                                          int use_bias) {
    extern __shared__ char smem[];
    const uint32_t sb = smem_u32(smem);
    const int tid = (int)threadIdx.x;
    const int lane = tid & 31;
    const int wid = tid >> 5;
    const int wm = wid & 1;   // 0..1 : 64-row half
    const int wn = wid >> 1;  // 0..3 : 32-col quarter

    const int m0 = (int)blockIdx.x * 128;
    const int n0 = (int)blockIdx.y * 128;

    // per-thread ldmatrix row bases
    const uint32_t a_row = sb + (uint32_t)((wm * 64 + (lane & 15)) * SSTRIDE)
                              + (uint32_t)((lane >> 4) * 16);
    const uint32_t b_row = sb + (uint32_t)((wn * 32 + (lane & 15)) * SSTRIDE)
                              + (uint32_t)((lane >> 4) * 16);

    float acc[4][4][4];
#pragma unroll
    for (int mt = 0; mt < 4; mt++)
#pragma unroll
        for (int nt = 0; nt < 4; nt++)
#pragma unroll
            for (int i = 0; i < 4; i++) acc[mt][nt][i] = 0.0f;

    const uint32_t AOFF[3] = {OFF_AH, OFF_AH, OFF_AL};
    const uint32_t BOFF[3] = {OFF_BH, OFF_BL, OFF_BH};

#pragma unroll 1
    for (int kc = 0; kc < 4; kc++) {
        const int koff = kc * 64;

        // ---- stage A (fp32 -> split bf16 hi/lo), 128 rows x 64 cols ----
#pragma unroll
        for (int it = 0; it < 8; it++) {
            const int idx = it * 256 + tid;       // 0..2047 float4 slots
            const int row = idx >> 4;
            const int c4 = idx & 15;
            float4 v = make_float4(0.f, 0.f, 0.f, 0.f);
            if (m0 + row < Mlim)
                v = *reinterpret_cast<const float4*>(
                        A + (size_t)(m0 + row) * 256 + koff + c4 * 4);
            const float hx = __bfloat162float(__float2bfloat16_rn(v.x));
            const float hy = __bfloat162float(__float2bfloat16_rn(v.y));
            const float hz = __bfloat162float(__float2bfloat16_rn(v.z));
            const float hw = __bfloat162float(__float2bfloat16_rn(v.w));
            uint2 hi, lo;
            hi.x = pack_bf16x2(hx, hy);
            hi.y = pack_bf16x2(hz, hw);
            lo.x = pack_bf16x2(v.x - hx, v.y - hy);
            lo.y = pack_bf16x2(v.z - hz, v.w - hw);
            const int dst = row * SSTRIDE + c4 * 8;
            *reinterpret_cast<uint2*>(smem + OFF_AH + dst) = hi;
            *reinterpret_cast<uint2*>(smem + OFF_AL + dst) = lo;
        }
        // ---- stage B hi/lo (pre-split bf16), 128 rows x 64 cols ----
#pragma unroll
        for (int it = 0; it < 4; it++) {
            const int idx = it * 256 + tid;       // 0..1023 uint4 slots
            const int row = idx >> 3;
            const int c8 = idx & 7;
            const size_t src = (size_t)(n0 + row) * 256 + koff + c8 * 8;
            const int dst = row * SSTRIDE + c8 * 16;
            *reinterpret_cast<uint4*>(smem + OFF_BH + dst) =
                *reinterpret_cast<const uint4*>(Bh + src);
            *reinterpret_cast<uint4*>(smem + OFF_BL + dst) =
                *reinterpret_cast<const uint4*>(Bl + src);
        }
        __syncthreads();

        // ---- 3 split terms x 4 k16 steps ----
#pragma unroll
        for (int t = 0; t < 3; t++) {
            const uint32_t ab = a_row + AOFF[t];
            const uint32_t bb = b_row + BOFF[t];
#pragma unroll
            for (int ks = 0; ks < 4; ks++) {
                uint32_t af[4][4];
#pragma unroll
                for (int mt = 0; mt < 4; mt++)
                    ldmatrix_x4(af[mt], ab + mt * (16 * SSTRIDE) + ks * 32);
                uint32_t bf[2][4];
#pragma unroll
                for (int np = 0; np < 2; np++)
                    ldmatrix_x4(bf[np], bb + np * (16 * SSTRIDE) + ks * 32);
#pragma unroll
                for (int mt = 0; mt < 4; mt++) {
                    mma16816(acc[mt][0], af[mt], bf[0][0], bf[0][2]);
                    mma16816(acc[mt][1], af[mt], bf[0][1], bf[0][3]);
                    mma16816(acc[mt][2], af[mt], bf[1][0], bf[1][2]);
                    mma16816(acc[mt][3], af[mt], bf[1][1], bf[1][3]);
                }
            }
        }
        __syncthreads();
    }

    // ---- epilogue ----
#pragma unroll
    for (int mt = 0; mt < 4; mt++) {
        const int r0 = m0 + wm * 64 + mt * 16 + (lane >> 2);
#pragma unroll
        for (int nt = 0; nt < 4; nt++) {
            const int col = n0 + wn * 32 + nt * 8 + (lane & 3) * 2;
            float b0 = 0.f, b1 = 0.f;
            if (use_bias) { b0 = g_b1[col]; b1 = g_b1[col + 1]; }
            if (r0 < Mlim) {
                float2 v = make_float2(acc[mt][nt][0] + b0, acc[mt][nt][1] + b1);
                *reinterpret_cast<float2*>(C + (size_t)r0 * 1024 + col) = v;
            }
            if (r0 + 8 < Mlim) {
                float2 v = make_float2(acc[mt][nt][2] + b0, acc[mt][nt][3] + b1);
                *reinterpret_cast<float2*>(C + (size_t)(r0 + 8) * 1024 + col) = v;
            }
        }
    }
}

__global__ void __launch_bounds__(256, 2) gemm_init_k(const float* __restrict__ X,
                                                      int M) {
    gemm_body(X, g_W1h, g_W1l, g_Y, M, 1);
}
__global__ void __launch_bounds__(256, 2) gemm_rec_k(int cs, int rows) {
    gemm_body(g_h + (size_t)cs * 256, g_W2h, g_W2l, g_G, rows, 0);
}

// ---------------------------------------------------------------------------
__global__ void pack_weights_kernel(const float* __restrict__ W_ioux,
                                    const float* __restrict__ b_ioux,
                                    const float* __restrict__ W_iouh,
                                    const float* __restrict__ b_iouh,
                                    const float* __restrict__ W_fx,
                                    const float* __restrict__ b_fx,
                                    const float* __restrict__ W_fh,
                                    const float* __restrict__ b_fh) {
    const int i = blockIdx.x * blockDim.x + threadIdx.x;
    if (i >= 1024 * 256) return;
    const int r = i >> 8;
    const int c = i & 255;
    const float w1 = (r < 768) ? W_ioux[i] : W_fx[(r - 768) * 256 + c];
    const float w2 = (r < 768) ? W_iouh[i] : W_fh[(r - 768) * 256 + c];
    const __nv_bfloat16 h1 = __float2bfloat16_rn(w1);
    const __nv_bfloat16 h2 = __float2bfloat16_rn(w2);
    g_W1h[i] = h1;
    g_W1l[i] = __float2bfloat16_rn(w1 - __bfloat162float(h1));
    g_W2h[i] = h2;
    g_W2l[i] = __float2bfloat16_rn(w2 - __bfloat162float(h2));
    if (c == 0)
        g_b1[r] = (r < 768) ? (b_ioux[r] + b_iouh[r])
                            : (b_fx[r - 768] + b_fh[r - 768]);
}

// ---------------------------------------------------------------------------
__global__ void leaf_kernel(int start) {
    const int n = start + (int)blockIdx.x;
    const int d = (int)threadIdx.x;
    const float* Yn = g_Y + (size_t)n * 1024;
    const float cv = sigmoidf_(Yn[d]) * tanhf(Yn[512 + d]);
    const float hv = sigmoidf_(Yn[256 + d]) * tanhf(cv);
    const size_t o = (size_t)n * 256 + d;
    g_c[o] = cv;
    g_h[o] = hv;
}

__global__ void combine_kernel(int start, int cs, float* __restrict__ out,
                               int is_root) {
    const int j = (int)blockIdx.x;
    const int d = (int)threadIdx.x;
    const int n = start + j;
    const float* Yn = g_Y + (size_t)n * 1024;
    const float* Gl = g_G + (size_t)(2 * j) * 1024;
    const float* Gr = g_G + (size_t)(2 * j + 1) * 1024;

    const float iv = Yn[d] + Gl[d] + Gr[d];
    const float ov = Yn[256 + d] + Gl[256 + d] + Gr[256 + d];
    const float uv = Yn[512 + d] + Gl[512 + d] + Gr[512 + d];
    const float fxv = Yn[768 + d];
    const float fl = sigmoidf_(Gl[768 + d] + fxv);
    const float fr = sigmoidf_(Gr[768 + d] + fxv);
    const float cl = g_c[(size_t)(cs + 2 * j) * 256 + d];
    const float cr = g_c[(size_t)(cs + 2 * j + 1) * 256 + d];

    const float cv = sigmoidf_(iv) * tanhf(uv) + fl * cl + fr * cr;
    const float hv = sigmoidf_(ov) * tanhf(cv);
    const size_t o = (size_t)n * 256 + d;
    g_c[o] = cv;
    g_h[o] = hv;
    if (is_root) {
        out[d] = cv;
        out[256 + d] = hv;
    }
}

// ---------------------------------------------------------------------------
extern "C" void kernel_launch(void* const* d_in, const int* in_sizes, int n_in,
                              void* d_out, int out_size) {
    const float* X      = (const float*)d_in[0];
    const float* W_ioux = (const float*)d_in[1];
    const float* b_ioux = (const float*)d_in[2];
    const float* W_iouh = (const float*)d_in[3];
    const float* b_iouh = (const float*)d_in[4];
    const float* W_fx   = (const float*)d_in[5];
    const float* b_fx   = (const float*)d_in[6];
    const float* W_fh   = (const float*)d_in[7];
    const float* b_fh   = (const float*)d_in[8];
    float* out = (float*)d_out;

    cudaFuncSetAttribute(gemm_init_k,
                         cudaFuncAttributeMaxDynamicSharedMemorySize, SMEM_BYTES);
    cudaFuncSetAttribute(gemm_rec_k,
                         cudaFuncAttributeMaxDynamicSharedMemorySize, SMEM_BYTES);

    pack_weights_kernel<<<(1024 * 256 + 255) / 256, 256>>>(
        W_ioux, b_ioux, W_iouh, b_iouh, W_fx, b_fx, W_fh, b_fh);

    // Y = X @ W1^T + b1   (M = 131071, N = 1024)
    gemm_init_k<<<dim3(1024, 8), 256, SMEM_BYTES>>>(X, NN);

    // leaves: level 16
    leaf_kernel<<<65536, 256>>>(65535);

    for (int lvl = 15; lvl >= 0; lvl--) {
        const int count = 1 << lvl;
        const int start = count - 1;
        const int cs = 2 * start + 1;
        const int rows = 2 * count;
        gemm_rec_k<<<dim3((rows + 127) / 128, 8), 256, SMEM_BYTES>>>(cs, rows);
        combine_kernel<<<count, 256>>>(start, cs, out, lvl == 0 ? 1 : 0);
    }
}

// round 6
// speedup vs baseline: 2.4886x; 2.0478x over previous
#include <cuda_runtime.h>
#include <cuda_bf16.h>
#include <math.h>
#include <stdint.h>

// ---------------------------------------------------------------------------
// ChildSumTreeLSTM, perfect binary tree N = 131071 = 2^17 - 1, dims 256/256.
//
//   Y[N,1024]   = X @ [W_ioux; W_fx]^T + folded biases          (HMMA)
//   per level:  Gf[2c,256]   = h_children @ W_fh^T              (HMMA)
//               Giou[c,768]  = (h_l + h_r) @ W_iouh^T           (HMMA, hsum trick)
//               combine -> c,h of parents (+ next level's hsum)
//
// GEMMs: mma.sync.m16n8k16 bf16->fp32, fp32 operands via hi/lo bf16 split:
//   A*B ~= Ah*Bh + Ah*Bl + Al*Bh
// A operands are pre-split in gmem so the GEMM stages with pure cp.async,
// double-buffered (2 stages x K-chunk 32).
// ---------------------------------------------------------------------------

#define NN 131071

// ---------------- device scratch (no allocations allowed) ------------------
static __device__ float         g_Y[(size_t)131072 * 1024];
static __device__ float         g_Gf[(size_t)65536 * 256];
static __device__ float         g_Giou[(size_t)32768 * 768];
static __device__ float         g_c[(size_t)131072 * 256];
static __device__ __nv_bfloat16 g_hh[(size_t)131072 * 256];
static __device__ __nv_bfloat16 g_hl[(size_t)131072 * 256];
static __device__ __nv_bfloat16 g_hsh[(size_t)65536 * 256];
static __device__ __nv_bfloat16 g_hsl[(size_t)65536 * 256];
static __device__ __nv_bfloat16 g_Xh[(size_t)131072 * 256];  // row NN stays 0
static __device__ __nv_bfloat16 g_Xl[(size_t)131072 * 256];
static __device__ __nv_bfloat16 g_W1h[1024 * 256];
static __device__ __nv_bfloat16 g_W1l[1024 * 256];
static __device__ __nv_bfloat16 g_W2h[1024 * 256];
static __device__ __nv_bfloat16 g_W2l[1024 * 256];
static __device__ float         g_b1[1024];

// ---------------- helpers ---------------------------------------------------
__device__ __forceinline__ float sigmoidf_(float x) { return 1.0f / (1.0f + expf(-x)); }

__device__ __forceinline__ uint32_t smem_u32(const void* p) {
    uint32_t a;
    asm("{ .reg .u64 t; cvta.to.shared.u64 t, %1; cvt.u32.u64 %0, t; }"
        : "=r"(a) : "l"(p));
    return a;
}

__device__ __forceinline__ void split2(float v, __nv_bfloat16& hi, __nv_bfloat16& lo) {
    hi = __float2bfloat16_rn(v);
    lo = __float2bfloat16_rn(v - __bfloat162float(hi));
}

__device__ __forceinline__ void ldmatrix_x4(uint32_t* r, uint32_t addr) {
    asm volatile("ldmatrix.sync.aligned.m8n8.x4.shared.b16 {%0,%1,%2,%3}, [%4];"
                 : "=r"(r[0]), "=r"(r[1]), "=r"(r[2]), "=r"(r[3]) : "r"(addr));
}

__device__ __forceinline__ void mma16816(float* d, const uint32_t* a,
                                         uint32_t b0, uint32_t b1) {
    asm volatile(
        "mma.sync.aligned.m16n8k16.row.col.f32.bf16.bf16.f32 "
        "{%0,%1,%2,%3}, {%4,%5,%6,%7}, {%8,%9}, {%0,%1,%2,%3};"
        : "+f"(d[0]), "+f"(d[1]), "+f"(d[2]), "+f"(d[3])
        : "r"(a[0]), "r"(a[1]), "r"(a[2]), "r"(a[3]), "r"(b0), "r"(b1));
}

__device__ __forceinline__ void cp16(uint32_t dst, const void* src) {
    asm volatile("cp.async.cg.shared.global [%0], [%1], 16;"
                 :: "r"(dst), "l"(__cvta_generic_to_global(src)));
}
#define CP_COMMIT() asm volatile("cp.async.commit_group;" ::: "memory")
#define CP_WAIT1()  asm volatile("cp.async.wait_group 1;" ::: "memory")

// ---------------- GEMM tile config ------------------------------------------
// 128(m) x 128(n) tile, K = 256 in 8 chunks of 32, 2-stage cp.async pipeline.
// Panel row = 32 bf16 = 64 B, padded to 80 B (conflict-free ldmatrix).
#define PSTRIDE 80
#define PANEL   (128 * PSTRIDE)   // 10240
#define STAGE   (4 * PANEL)       // 40960: Ah | Al | Bh | Bl
#define SMEM_BYTES (2 * STAGE)    // 81920 -> 2 CTAs/SM

// All A/B/C pointers are pre-offset to the tile. Row strides: A/B 256, C ldc.
// All arrays are padded device globals -> no bounds checks anywhere.
__device__ __forceinline__ void gemm_tile(const __nv_bfloat16* __restrict__ Ah,
                                          const __nv_bfloat16* __restrict__ Al,
                                          const __nv_bfloat16* __restrict__ Bh,
                                          const __nv_bfloat16* __restrict__ Bl,
                                          float* __restrict__ C, int ldc,
                                          const float* __restrict__ bias) {
    extern __shared__ char smem[];
    const uint32_t sb = smem_u32(smem);
    const int tid = (int)threadIdx.x;
    const int lane = tid & 31;
    const int wid = tid >> 5;
    const int wm = wid & 1;   // 64-row half
    const int wn = wid >> 1;  // 32-col quarter

    float acc[4][4][4];
#pragma unroll
    for (int mt = 0; mt < 4; mt++)
#pragma unroll
        for (int nt = 0; nt < 4; nt++)
#pragma unroll
            for (int i = 0; i < 4; i++) acc[mt][nt][i] = 0.0f;

    auto issue = [&](int kc) {
        const uint32_t sbase = sb + (uint32_t)(kc & 1) * STAGE;
        const int koff = kc * 32;
#pragma unroll
        for (int it = 0; it < 2; it++) {
            const int idx = it * 256 + tid;  // 0..511 16B-slots per panel
            const int row = idx >> 2;
            const int c16 = idx & 3;
            const uint32_t doff = (uint32_t)(row * PSTRIDE + c16 * 16);
            const size_t goff = (size_t)row * 256 + koff + c16 * 8;
            cp16(sbase + doff,             Ah + goff);
            cp16(sbase + PANEL + doff,     Al + goff);
            cp16(sbase + 2 * PANEL + doff, Bh + goff);
            cp16(sbase + 3 * PANEL + doff, Bl + goff);
        }
        CP_COMMIT();
    };

    issue(0);
    issue(1);

#pragma unroll 1
    for (int kc = 0; kc < 8; kc++) {
        CP_WAIT1();
        __syncthreads();
        const uint32_t sbase = sb + (uint32_t)(kc & 1) * STAGE;
        const uint32_t arow = sbase +
            (uint32_t)((wm * 64 + (lane & 15)) * PSTRIDE + (lane >> 4) * 16);
        const uint32_t brow = sbase + 2 * PANEL +
            (uint32_t)((wn * 32 + (lane & 15)) * PSTRIDE + (lane >> 4) * 16);

#pragma unroll
        for (int ks = 0; ks < 2; ks++) {
            const uint32_t kb = (uint32_t)(ks * 32);
            uint32_t ah[4][4], al[4][4], bb[2][4];
#pragma unroll
            for (int mt = 0; mt < 4; mt++) {
                ldmatrix_x4(ah[mt], arow + mt * (16 * PSTRIDE) + kb);
                ldmatrix_x4(al[mt], arow + PANEL + mt * (16 * PSTRIDE) + kb);
            }
            // Bh: both hi- and lo-A terms
            ldmatrix_x4(bb[0], brow + kb);
            ldmatrix_x4(bb[1], brow + 16 * PSTRIDE + kb);
#pragma unroll
            for (int mt = 0; mt < 4; mt++) {
                mma16816(acc[mt][0], ah[mt], bb[0][0], bb[0][2]);
                mma16816(acc[mt][1], ah[mt], bb[0][1], bb[0][3]);
                mma16816(acc[mt][2], ah[mt], bb[1][0], bb[1][2]);
                mma16816(acc[mt][3], ah[mt], bb[1][1], bb[1][3]);
                mma16816(acc[mt][0], al[mt], bb[0][0], bb[0][2]);
                mma16816(acc[mt][1], al[mt], bb[0][1], bb[0][3]);
                mma16816(acc[mt][2], al[mt], bb[1][0], bb[1][2]);
                mma16816(acc[mt][3], al[mt], bb[1][1], bb[1][3]);
            }
            // Bl: hi-A term only
            ldmatrix_x4(bb[0], brow + PANEL + kb);
            ldmatrix_x4(bb[1], brow + PANEL + 16 * PSTRIDE + kb);
#pragma unroll
            for (int mt = 0; mt < 4; mt++) {
                mma16816(acc[mt][0], ah[mt], bb[0][0], bb[0][2]);
                mma16816(acc[mt][1], ah[mt], bb[0][1], bb[0][3]);
                mma16816(acc[mt][2], ah[mt], bb[1][0], bb[1][2]);
                mma16816(acc[mt][3], ah[mt], bb[1][1], bb[1][3]);
            }
        }
        __syncthreads();
        if (kc + 2 < 8) issue(kc + 2);
    }

    // ---- epilogue (all target rows exist: arrays padded) ----
#pragma unroll
    for (int mt = 0; mt < 4; mt++) {
        const int r0 = wm * 64 + mt * 16 + (lane >> 2);
#pragma unroll
        for (int nt = 0; nt < 4; nt++) {
            const int col = wn * 32 + nt * 8 + (lane & 3) * 2;
            float b0 = 0.f, b1 = 0.f;
            if (bias) { b0 = bias[col]; b1 = bias[col + 1]; }
            *reinterpret_cast<float2*>(C + (size_t)r0 * ldc + col) =
                make_float2(acc[mt][nt][0] + b0, acc[mt][nt][1] + b1);
            *reinterpret_cast<float2*>(C + (size_t)(r0 + 8) * ldc + col) =
                make_float2(acc[mt][nt][2] + b0, acc[mt][nt][3] + b1);
        }
    }
}

// ---------------------------------------------------------------------------
__global__ void __launch_bounds__(256, 2) gemm_init_k() {
    const size_t m0 = (size_t)blockIdx.x * 128;
    const size_t n0 = (size_t)blockIdx.y * 128;
    gemm_tile(g_Xh + m0 * 256, g_Xl + m0 * 256,
              g_W1h + n0 * 256, g_W1l + n0 * 256,
              g_Y + m0 * 1024 + n0, 1024, g_b1 + n0);
}

// One launch per level covering both recurrent GEMMs:
//   f-gemm:   Gf[2c,256]  = h[cs..] @ W2[768:1024]^T   (tiles_f x 2 tiles)
//   iou-gemm: Giou[c,768] = hsum[start..] @ W2[0:768]^T (tiles_i x 6 tiles)
__global__ void __launch_bounds__(256, 2) gemm_rec_k(int cs, int start, int c) {
    const int tiles_f = (2 * c + 127) >> 7;
    const int bid = (int)blockIdx.x;
    if (bid < tiles_f * 2) {
        const size_t mt = (size_t)(bid >> 1);
        const size_t nt = (size_t)(bid & 1);
        gemm_tile(g_hh + ((size_t)cs + mt * 128) * 256,
                  g_hl + ((size_t)cs + mt * 128) * 256,
                  g_W2h + (768 + nt * 128) * 256,
                  g_W2l + (768 + nt * 128) * 256,
                  g_Gf + mt * 128 * 256 + nt * 128, 256, nullptr);
    } else {
        const int r = bid - tiles_f * 2;
        const size_t mt = (size_t)(r / 6);
        const size_t nt = (size_t)(r % 6);
        gemm_tile(g_hsh + ((size_t)start + mt * 128) * 256,
                  g_hsl + ((size_t)start + mt * 128) * 256,
                  g_W2h + nt * 128 * 256, g_W2l + nt * 128 * 256,
                  g_Giou + mt * 128 * 768 + nt * 128, 768, nullptr);
    }
}

// ---------------------------------------------------------------------------
__global__ void pack_weights_k(const float* __restrict__ W_ioux,
                               const float* __restrict__ b_ioux,
                               const float* __restrict__ W_iouh,
                               const float* __restrict__ b_iouh,
                               const float* __restrict__ W_fx,
                               const float* __restrict__ b_fx,
                               const float* __restrict__ W_fh,
                               const float* __restrict__ b_fh) {
    const int i = blockIdx.x * blockDim.x + threadIdx.x;
    if (i >= 1024 * 256) return;
    const int r = i >> 8;
    const int cc = i & 255;
    const float w1 = (r < 768) ? W_ioux[i] : W_fx[(r - 768) * 256 + cc];
    const float w2 = (r < 768) ? W_iouh[i] : W_fh[(r - 768) * 256 + cc];
    __nv_bfloat16 hi, lo;
    split2(w1, hi, lo); g_W1h[i] = hi; g_W1l[i] = lo;
    split2(w2, hi, lo); g_W2h[i] = hi; g_W2l[i] = lo;
    if (cc == 0)
        g_b1[r] = (r < 768) ? (b_ioux[r] + b_iouh[r])
                            : (b_fx[r - 768] + b_fh[r - 768]);
}

__global__ void convert_x_k(const float* __restrict__ X) {
    const size_t i = ((size_t)blockIdx.x * 256 + threadIdx.x) * 4;
    if (i >= (size_t)NN * 256) return;
    const float4 v = *reinterpret_cast<const float4*>(X + i);
    __nv_bfloat16 h[4], l[4];
    split2(v.x, h[0], l[0]);
    split2(v.y, h[1], l[1]);
    split2(v.z, h[2], l[2]);
    split2(v.w, h[3], l[3]);
    *reinterpret_cast<uint2*>(g_Xh + i) = *reinterpret_cast<uint2*>(h);
    *reinterpret_cast<uint2*>(g_Xl + i) = *reinterpret_cast<uint2*>(l);
}

// ---------------------------------------------------------------------------
// Leaves (level 16): one block per sibling pair; writes c, split h, parent hsum.
__global__ void leaf_k() {
    const int j = (int)blockIdx.x;   // 0..32767
    const int d = (int)threadIdx.x;  // 0..255
    const int n0 = 65535 + 2 * j;
    const float* Y0 = g_Y + (size_t)n0 * 1024;
    const float* Y1 = Y0 + 1024;

    const float c0 = sigmoidf_(Y0[d]) * tanhf(Y0[512 + d]);
    const float h0 = sigmoidf_(Y0[256 + d]) * tanhf(c0);
    const float c1 = sigmoidf_(Y1[d]) * tanhf(Y1[512 + d]);
    const float h1 = sigmoidf_(Y1[256 + d]) * tanhf(c1);

    const size_t o0 = (size_t)n0 * 256 + d;
    g_c[o0] = c0;
    g_c[o0 + 256] = c1;
    __nv_bfloat16 hi, lo;
    split2(h0, hi, lo); g_hh[o0] = hi; g_hl[o0] = lo;
    split2(h1, hi, lo); g_hh[o0 + 256] = hi; g_hl[o0 + 256] = lo;
    split2(h0 + h1, hi, lo);
    const size_t op = (size_t)(32767 + j) * 256 + d;
    g_hsh[op] = hi;
    g_hsl[op] = lo;
}

// Internal levels lvl >= 1: one block per sibling pair of parents.
__global__ void combine_k(int start, int cs, int pstart) {
    const int b = (int)blockIdx.x;
    const int d = (int)threadIdx.x;
    const int i0 = 2 * b;
    const int n0 = start + i0;
    const float* Y0 = g_Y + (size_t)n0 * 1024;
    const float* Y1 = Y0 + 1024;
    const float* Gi0 = g_Giou + (size_t)i0 * 768;
    const float* Gi1 = Gi0 + 768;
    const float* Gf0 = g_Gf + (size_t)(4 * b) * 256;  // rows 4b..4b+3
    const float* cch = g_c + (size_t)(cs + 4 * b) * 256;

    // parent 0
    const float fx0 = Y0[768 + d];
    const float fl0 = sigmoidf_(Gf0[d] + fx0);
    const float fr0 = sigmoidf_(Gf0[256 + d] + fx0);
    const float c0 = sigmoidf_(Y0[d] + Gi0[d]) * tanhf(Y0[512 + d] + Gi0[512 + d])
                   + fl0 * cch[d] + fr0 * cch[256 + d];
    const float h0 = sigmoidf_(Y0[256 + d] + Gi0[256 + d]) * tanhf(c0);
    // parent 1
    const float fx1 = Y1[768 + d];
    const float fl1 = sigmoidf_(Gf0[512 + d] + fx1);
    const float fr1 = sigmoidf_(Gf0[768 + d] + fx1);
    const float c1 = sigmoidf_(Y1[d] + Gi1[d]) * tanhf(Y1[512 + d] + Gi1[512 + d])
                   + fl1 * cch[512 + d] + fr1 * cch[768 + d];
    const float h1 = sigmoidf_(Y1[256 + d] + Gi1[256 + d]) * tanhf(c1);

    const size_t o0 = (size_t)n0 * 256 + d;
    g_c[o0] = c0;
    g_c[o0 + 256] = c1;
    __nv_bfloat16 hi, lo;
    split2(h0, hi, lo); g_hh[o0] = hi; g_hl[o0] = lo;
    split2(h1, hi, lo); g_hh[o0 + 256] = hi; g_hl[o0 + 256] = lo;
    split2(h0 + h1, hi, lo);
    const size_t op = (size_t)(pstart + b) * 256 + d;
    g_hsh[op] = hi;
    g_hsl[op] = lo;
}

// Root (level 0): single node, writes the output.
__global__ void root_k(float* __restrict__ out) {
    const int d = (int)threadIdx.x;
    const float* Y0 = g_Y;
    const float* Gi = g_Giou;
    const float* Gf0 = g_Gf;
    const float fx = Y0[768 + d];
    const float fl = sigmoidf_(Gf0[d] + fx);
    const float fr = sigmoidf_(Gf0[256 + d] + fx);
    const float cl = g_c[256 + d];        // node 1
    const float cr = g_c[512 + d];        // node 2
    const float cv = sigmoidf_(Y0[d] + Gi[d]) * tanhf(Y0[512 + d] + Gi[512 + d])
                   + fl * cl + fr * cr;
    const float hv = sigmoidf_(Y0[256 + d] + Gi[256 + d]) * tanhf(cv);
    out[d] = cv;
    out[256 + d] = hv;
}

// ---------------------------------------------------------------------------
extern "C" void kernel_launch(void* const* d_in, const int* in_sizes, int n_in,
                              void* d_out, int out_size) {
    const float* X      = (const float*)d_in[0];
    const float* W_ioux = (const float*)d_in[1];
    const float* b_ioux = (const float*)d_in[2];
    const float* W_iouh = (const float*)d_in[3];
    const float* b_iouh = (const float*)d_in[4];
    const float* W_fx   = (const float*)d_in[5];
    const float* b_fx   = (const float*)d_in[6];
    const float* W_fh   = (const float*)d_in[7];
    const float* b_fh   = (const float*)d_in[8];
    float* out = (float*)d_out;

    cudaFuncSetAttribute(gemm_init_k,
                         cudaFuncAttributeMaxDynamicSharedMemorySize, SMEM_BYTES);
    cudaFuncSetAttribute(gemm_rec_k,
                         cudaFuncAttributeMaxDynamicSharedMemorySize, SMEM_BYTES);

    pack_weights_k<<<1024, 256>>>(W_ioux, b_ioux, W_iouh, b_iouh,
                                  W_fx, b_fx, W_fh, b_fh);
    convert_x_k<<<32769, 256>>>(X);

    // Y = X @ W1^T + b1
    gemm_init_k<<<dim3(1024, 8), 256, SMEM_BYTES>>>();

    // leaves (level 16)
    leaf_k<<<32768, 256>>>();

    for (int lvl = 15; lvl >= 1; lvl--) {
        const int c = 1 << lvl;
        const int start = c - 1;
        const int cs = 2 * c - 1;
        const int tiles_f = (2 * c + 127) >> 7;
        const int tiles_i = (c + 127) >> 7;
        gemm_rec_k<<<tiles_f * 2 + tiles_i * 6, 256, SMEM_BYTES>>>(cs, start, c);
        combine_k<<<c / 2, 256>>>(start, cs, (1 << (lvl - 1)) - 1);
    }
    // level 0 (root)
    gemm_rec_k<<<8, 256, SMEM_BYTES>>>(1, 0, 1);
    root_k<<<1, 256>>>(out);
}

// round 7
// speedup vs baseline: 3.7465x; 1.5055x over previous
#include <cuda_runtime.h>
#include <cuda_fp16.h>
#include <math.h>
#include <stdint.h>

// ---------------------------------------------------------------------------
// ChildSumTreeLSTM, perfect binary tree N = 131071 = 2^17 - 1, dims 256/256.
//
//   Y[N,1024]   = X @ [W_ioux; W_fx]^T + folded biases          (HMMA)
//                 (fx slab computed only for internal-node rows)
//   per level:  Gf[2c,256]   = h_children @ W_fh^T              (HMMA)
//               Giou[c,768]  = (h_l + h_r) @ W_iouh^T           (HMMA, hsum)
//               combine -> c,h of parents (+ next level's hsum)
//
// GEMMs: mma.sync.m16n8k16 f16->fp32, 2-term split:
//   A in fp16 (single), B = Bh + Bl (fp16 hi/lo)  =>  D = Ah*Bh + Ah*Bl
//   error ~= fp16 rounding of A ~ 2^-12 (validated 1:1 error model).
// 3-stage cp.async pipeline, K-chunks of 32.
// ---------------------------------------------------------------------------

#define NN 131071

// ---------------- device scratch (no allocations allowed) ------------------
static __device__ float  g_Y[(size_t)131072 * 1024];
static __device__ float  g_Gf[(size_t)65536 * 256];
static __device__ float  g_Giou[(size_t)32768 * 768];
static __device__ float  g_c[(size_t)131072 * 256];
static __device__ __half g_h[(size_t)131072 * 256];
static __device__ __half g_hs[(size_t)65536 * 256];
static __device__ __half g_X[(size_t)131072 * 256];   // row NN stays 0
static __device__ __half g_W1h[1024 * 256];
static __device__ __half g_W1l[1024 * 256];
static __device__ __half g_W2h[1024 * 256];
static __device__ __half g_W2l[1024 * 256];
static __device__ float  g_b1[1024];

// ---------------- helpers ---------------------------------------------------
__device__ __forceinline__ float fsig(float x) {
    return __fdividef(1.0f, 1.0f + __expf(-x));
}
__device__ __forceinline__ float ftanh(float x) {
    x = fminf(fmaxf(x, -30.0f), 30.0f);
    const float e = __expf(2.0f * x);
    return __fdividef(e - 1.0f, e + 1.0f);
}

__device__ __forceinline__ uint32_t smem_u32(const void* p) {
    uint32_t a;
    asm("{ .reg .u64 t; cvta.to.shared.u64 t, %1; cvt.u32.u64 %0, t; }"
        : "=r"(a) : "l"(p));
    return a;
}

__device__ __forceinline__ void ldmatrix_x4(uint32_t* r, uint32_t addr) {
    asm volatile("ldmatrix.sync.aligned.m8n8.x4.shared.b16 {%0,%1,%2,%3}, [%4];"
                 : "=r"(r[0]), "=r"(r[1]), "=r"(r[2]), "=r"(r[3]) : "r"(addr));
}

__device__ __forceinline__ void mma16816(float* d, const uint32_t* a,
                                         uint32_t b0, uint32_t b1) {
    asm volatile(
        "mma.sync.aligned.m16n8k16.row.col.f32.f16.f16.f32 "
        "{%0,%1,%2,%3}, {%4,%5,%6,%7}, {%8,%9}, {%0,%1,%2,%3};"
        : "+f"(d[0]), "+f"(d[1]), "+f"(d[2]), "+f"(d[3])
        : "r"(a[0]), "r"(a[1]), "r"(a[2]), "r"(a[3]), "r"(b0), "r"(b1));
}

__device__ __forceinline__ void cp16(uint32_t dst, const void* src) {
    asm volatile("cp.async.cg.shared.global [%0], [%1], 16;"
                 :: "r"(dst), "l"(__cvta_generic_to_global(src)));
}
#define CP_COMMIT() asm volatile("cp.async.commit_group;" ::: "memory")
#define CP_WAIT2()  asm volatile("cp.async.wait_group 2;" ::: "memory")

__device__ __forceinline__ void store_h4(__half* p, float a, float b,
                                         float c, float d) {
    union { __half2 h2[2]; uint2 u; } t;
    t.h2[0] = __floats2half2_rn(a, b);
    t.h2[1] = __floats2half2_rn(c, d);
    *reinterpret_cast<uint2*>(p) = t.u;
}

// ---------------- GEMM tile config ------------------------------------------
// 128(m) x 128(n) tile, K = 256 in 8 chunks of 32, 3-stage cp.async pipeline.
// Panel row = 32 halves = 64 B, padded to 80 B (conflict-free ldmatrix).
#define PSTRIDE 80
#define PANEL   (128 * PSTRIDE)    // 10240
#define STAGE   (3 * PANEL)        // 30720: A | Bh | Bl
#define SMEM_BYTES (3 * STAGE)     // 92160 -> 2 CTAs/SM

// Pointers pre-offset to tile. Row stride A/B = 256. Padded arrays: no guards.
__device__ __forceinline__ void gemm_tile(const __half* __restrict__ A,
                                          const __half* __restrict__ Bh,
                                          const __half* __restrict__ Bl,
                                          float* __restrict__ C, int ldc,
                                          const float* __restrict__ bias) {
    extern __shared__ char smem[];
    const uint32_t sb = smem_u32(smem);
    const int tid = (int)threadIdx.x;
    const int lane = tid & 31;
    const int wid = tid >> 5;
    const int wm = wid & 1;   // 64-row half
    const int wn = wid >> 1;  // 32-col quarter

    float acc[4][4][4];
#pragma unroll
    for (int mt = 0; mt < 4; mt++)
#pragma unroll
        for (int nt = 0; nt < 4; nt++)
#pragma unroll
            for (int i = 0; i < 4; i++) acc[mt][nt][i] = 0.0f;

    const __half* srcp[3] = {A, Bh, Bl};

    auto issue = [&](int kc) {
        const uint32_t sbase = sb + (uint32_t)(kc % 3) * STAGE;
        const int koff = kc * 32;
#pragma unroll
        for (int it = 0; it < 6; it++) {
            const int panel = it >> 1;
            const int slot = (it & 1) * 256 + tid;   // 0..511
            const int row = slot >> 2;
            const int c16 = slot & 3;
            cp16(sbase + (uint32_t)(panel * PANEL + row * PSTRIDE + c16 * 16),
                 srcp[panel] + (size_t)row * 256 + koff + c16 * 8);
        }
        CP_COMMIT();
    };

    issue(0);
    issue(1);
    issue(2);

#pragma unroll 1
    for (int kc = 0; kc < 8; kc++) {
        CP_WAIT2();
        __syncthreads();
        const uint32_t sbase = sb + (uint32_t)(kc % 3) * STAGE;
        const uint32_t arow = sbase +
            (uint32_t)((wm * 64 + (lane & 15)) * PSTRIDE + (lane >> 4) * 16);
        const uint32_t bbase = sbase + PANEL +
            (uint32_t)((wn * 32 + (lane & 15)) * PSTRIDE + (lane >> 4) * 16);

#pragma unroll
        for (int ks = 0; ks < 2; ks++) {
            const uint32_t kb = (uint32_t)(ks * 32);
            uint32_t ah[4][4], bh[2][4], bl[2][4];
#pragma unroll
            for (int mt = 0; mt < 4; mt++)
                ldmatrix_x4(ah[mt], arow + mt * (16 * PSTRIDE) + kb);
            ldmatrix_x4(bh[0], bbase + kb);
            ldmatrix_x4(bh[1], bbase + 16 * PSTRIDE + kb);
            ldmatrix_x4(bl[0], bbase + PANEL + kb);
            ldmatrix_x4(bl[1], bbase + PANEL + 16 * PSTRIDE + kb);
#pragma unroll
            for (int mt = 0; mt < 4; mt++) {
                mma16816(acc[mt][0], ah[mt], bh[0][0], bh[0][2]);
                mma16816(acc[mt][1], ah[mt], bh[0][1], bh[0][3]);
                mma16816(acc[mt][2], ah[mt], bh[1][0], bh[1][2]);
                mma16816(acc[mt][3], ah[mt], bh[1][1], bh[1][3]);
                mma16816(acc[mt][0], ah[mt], bl[0][0], bl[0][2]);
                mma16816(acc[mt][1], ah[mt], bl[0][1], bl[0][3]);
                mma16816(acc[mt][2], ah[mt], bl[1][0], bl[1][2]);
                mma16816(acc[mt][3], ah[mt], bl[1][1], bl[1][3]);
            }
        }
        __syncthreads();
        if (kc + 3 < 8) issue(kc + 3);
    }

    // ---- epilogue (all target rows exist: arrays padded) ----
#pragma unroll
    for (int mt = 0; mt < 4; mt++) {
        const int r0 = wm * 64 + mt * 16 + (lane >> 2);
#pragma unroll
        for (int nt = 0; nt < 4; nt++) {
            const int col = wn * 32 + nt * 8 + (lane & 3) * 2;
            float b0 = 0.f, b1 = 0.f;
            if (bias) { b0 = bias[col]; b1 = bias[col + 1]; }
            *reinterpret_cast<float2*>(C + (size_t)r0 * ldc + col) =
                make_float2(acc[mt][nt][0] + b0, acc[mt][nt][1] + b1);
            *reinterpret_cast<float2*>(C + (size_t)(r0 + 8) * ldc + col) =
                make_float2(acc[mt][nt][2] + b0, acc[mt][nt][3] + b1);
        }
    }
}

// ---------------------------------------------------------------------------
__global__ void __launch_bounds__(256, 2) gemm_init_k(int ny_off) {
    const size_t m0 = (size_t)blockIdx.x * 128;
    const size_t n0 = (size_t)(blockIdx.y + ny_off) * 128;
    gemm_tile(g_X + m0 * 256,
              g_W1h + n0 * 256, g_W1l + n0 * 256,
              g_Y + m0 * 1024 + n0, 1024, g_b1 + n0);
}

// One launch per level covering both recurrent GEMMs.
__global__ void __launch_bounds__(256, 2) gemm_rec_k(int cs, int start, int c) {
    const int tiles_f = (2 * c + 127) >> 7;
    const int bid = (int)blockIdx.x;
    if (bid < tiles_f * 2) {
        const size_t mt = (size_t)(bid >> 1);
        const size_t nt = (size_t)(bid & 1);
        gemm_tile(g_h + ((size_t)cs + mt * 128) * 256,
                  g_W2h + (768 + nt * 128) * 256,
                  g_W2l + (768 + nt * 128) * 256,
                  g_Gf + mt * 128 * 256 + nt * 128, 256, nullptr);
    } else {
        const int r = bid - tiles_f * 2;
        const size_t mt = (size_t)(r / 6);
        const size_t nt = (size_t)(r % 6);
        gemm_tile(g_hs + ((size_t)start + mt * 128) * 256,
                  g_W2h + nt * 128 * 256, g_W2l + nt * 128 * 256,
                  g_Giou + mt * 128 * 768 + nt * 128, 768, nullptr);
    }
}

// ---------------------------------------------------------------------------
__global__ void pack_weights_k(const float* __restrict__ W_ioux,
                               const float* __restrict__ b_ioux,
                               const float* __restrict__ W_iouh,
                               const float* __restrict__ b_iouh,
                               const float* __restrict__ W_fx,
                               const float* __restrict__ b_fx,
                               const float* __restrict__ W_fh,
                               const float* __restrict__ b_fh) {
    const int i = blockIdx.x * blockDim.x + threadIdx.x;
    if (i >= 1024 * 256) return;
    const int r = i >> 8;
    const int cc = i & 255;
    const float w1 = (r < 768) ? W_ioux[i] : W_fx[(r - 768) * 256 + cc];
    const float w2 = (r < 768) ? W_iouh[i] : W_fh[(r - 768) * 256 + cc];
    const __half h1 = __float2half_rn(w1);
    const __half h2 = __float2half_rn(w2);
    g_W1h[i] = h1;
    g_W1l[i] = __float2half_rn(w1 - __half2float(h1));
    g_W2h[i] = h2;
    g_W2l[i] = __float2half_rn(w2 - __half2float(h2));
    if (cc == 0)
        g_b1[r] = (r < 768) ? (b_ioux[r] + b_iouh[r])
                            : (b_fx[r - 768] + b_fh[r - 768]);
}

__global__ void convert_x_k(const float* __restrict__ X) {
    const size_t i = ((size_t)blockIdx.x * 256 + threadIdx.x) * 4;
    if (i >= (size_t)NN * 256) return;
    const float4 v = *reinterpret_cast<const float4*>(X + i);
    store_h4(g_X + i, v.x, v.y, v.z, v.w);
}

// ---------------------------------------------------------------------------
// Leaves (level 16): block = 4 sibling pairs x 64 lanes (float4 per lane).
__global__ void leaf_k() {
    const int tid = (int)threadIdx.x;
    const int p = tid >> 6;
    const int l = tid & 63;
    const int j = (int)blockIdx.x * 4 + p;   // pair id 0..32767
    const int d = l * 4;
    const int n0 = 65535 + 2 * j;
    const float* Y0 = g_Y + (size_t)n0 * 1024;
    const float* Y1 = Y0 + 1024;

    const float4 i0 = *(const float4*)(Y0 + d);
    const float4 o0 = *(const float4*)(Y0 + 256 + d);
    const float4 u0 = *(const float4*)(Y0 + 512 + d);
    const float4 i1 = *(const float4*)(Y1 + d);
    const float4 o1 = *(const float4*)(Y1 + 256 + d);
    const float4 u1 = *(const float4*)(Y1 + 512 + d);

    float c0[4], h0[4], c1[4], h1[4];
    const float* pi0 = &i0.x; const float* po0 = &o0.x; const float* pu0 = &u0.x;
    const float* pi1 = &i1.x; const float* po1 = &o1.x; const float* pu1 = &u1.x;
#pragma unroll
    for (int t = 0; t < 4; t++) {
        c0[t] = fsig(pi0[t]) * ftanh(pu0[t]);
        h0[t] = fsig(po0[t]) * ftanh(c0[t]);
        c1[t] = fsig(pi1[t]) * ftanh(pu1[t]);
        h1[t] = fsig(po1[t]) * ftanh(c1[t]);
    }

    const size_t b0 = (size_t)n0 * 256 + d;
    *(float4*)(g_c + b0) = make_float4(c0[0], c0[1], c0[2], c0[3]);
    *(float4*)(g_c + b0 + 256) = make_float4(c1[0], c1[1], c1[2], c1[3]);
    store_h4(g_h + b0, h0[0], h0[1], h0[2], h0[3]);
    store_h4(g_h + b0 + 256, h1[0], h1[1], h1[2], h1[3]);
    store_h4(g_hs + (size_t)(32767 + j) * 256 + d,
             h0[0] + h1[0], h0[1] + h1[1], h0[2] + h1[2], h0[3] + h1[3]);
}

// Internal levels lvl >= 1: block = 4 parent-pairs x 64 lanes.
__global__ void combine_k(int start, int cs, int pstart, int npairs) {
    const int tid = (int)threadIdx.x;
    const int p = tid >> 6;
    const int l = tid & 63;
    const int j = (int)blockIdx.x * 4 + p;   // parent-pair id
    if (j >= npairs) return;
    const int d = l * 4;
    const int n0 = start + 2 * j;
    const float* Y0 = g_Y + (size_t)n0 * 1024;
    const float* Y1 = Y0 + 1024;
    const float* Gi0 = g_Giou + (size_t)(2 * j) * 768;
    const float* Gi1 = Gi0 + 768;
    const float* Gf = g_Gf + (size_t)(4 * j) * 256;
    const float* cch = g_c + (size_t)(cs + 4 * j) * 256;

    const float4 yi0 = *(const float4*)(Y0 + d);
    const float4 yo0 = *(const float4*)(Y0 + 256 + d);
    const float4 yu0 = *(const float4*)(Y0 + 512 + d);
    const float4 yf0 = *(const float4*)(Y0 + 768 + d);
    const float4 yi1 = *(const float4*)(Y1 + d);
    const float4 yo1 = *(const float4*)(Y1 + 256 + d);
    const float4 yu1 = *(const float4*)(Y1 + 512 + d);
    const float4 yf1 = *(const float4*)(Y1 + 768 + d);
    const float4 gi0 = *(const float4*)(Gi0 + d);
    const float4 go0 = *(const float4*)(Gi0 + 256 + d);
    const float4 gu0 = *(const float4*)(Gi0 + 512 + d);
    const float4 gi1 = *(const float4*)(Gi1 + d);
    const float4 go1 = *(const float4*)(Gi1 + 256 + d);
    const float4 gu1 = *(const float4*)(Gi1 + 512 + d);
    const float4 gfl0 = *(const float4*)(Gf + d);
    const float4 gfr0 = *(const float4*)(Gf + 256 + d);
    const float4 gfl1 = *(const float4*)(Gf + 512 + d);
    const float4 gfr1 = *(const float4*)(Gf + 768 + d);
    const float4 cl0 = *(const float4*)(cch + d);
    const float4 cr0 = *(const float4*)(cch + 256 + d);
    const float4 cl1 = *(const float4*)(cch + 512 + d);
    const float4 cr1 = *(const float4*)(cch + 768 + d);

    float c0[4], h0[4], c1[4], h1[4];
    const float *a, *b, *cc2, *e, *f, *g, *hh, *kk;
#define ELT(t, yi, gi, yu, gu, yo, go, yf, gl, gr, cl, cr, co, ho)              \
    {                                                                           \
        a = &(yi).x; b = &(gi).x; cc2 = &(yu).x; e = &(gu).x;                   \
        f = &(yo).x; g = &(go).x; hh = &(yf).x;                                 \
        const float* pgl = &(gl).x; const float* pgr = &(gr).x;                 \
        const float* pcl = &(cl).x; const float* pcr = &(cr).x;                 \
        kk = hh;                                                                \
        const float fl = fsig(pgl[t] + kk[t]);                                  \
        const float fr = fsig(pgr[t] + kk[t]);                                  \
        co[t] = fsig(a[t] + b[t]) * ftanh(cc2[t] + e[t]) + fl * pcl[t] + fr * pcr[t]; \
        ho[t] = fsig(f[t] + g[t]) * ftanh(co[t]);                               \
    }
#pragma unroll
    for (int t = 0; t < 4; t++) {
        ELT(t, yi0, gi0, yu0, gu0, yo0, go0, yf0, gfl0, gfr0, cl0, cr0, c0, h0);
        ELT(t, yi1, gi1, yu1, gu1, yo1, go1, yf1, gfl1, gfr1, cl1, cr1, c1, h1);
    }
#undef ELT

    const size_t b0 = (size_t)n0 * 256 + d;
    *(float4*)(g_c + b0) = make_float4(c0[0], c0[1], c0[2], c0[3]);
    *(float4*)(g_c + b0 + 256) = make_float4(c1[0], c1[1], c1[2], c1[3]);
    store_h4(g_h + b0, h0[0], h0[1], h0[2], h0[3]);
    store_h4(g_h + b0 + 256, h1[0], h1[1], h1[2], h1[3]);
    store_h4(g_hs + (size_t)(pstart + j) * 256 + d,
             h0[0] + h1[0], h0[1] + h1[1], h0[2] + h1[2], h0[3] + h1[3]);
}

// Root (level 0): single node, writes the output.
__global__ void root_k(float* __restrict__ out) {
    const int d = (int)threadIdx.x;
    const float* Y0 = g_Y;
    const float* Gi = g_Giou;
    const float* Gf = g_Gf;
    const float fx = Y0[768 + d];
    const float fl = fsig(Gf[d] + fx);
    const float fr = fsig(Gf[256 + d] + fx);
    const float cl = g_c[256 + d];
    const float cr = g_c[512 + d];
    const float cv = fsig(Y0[d] + Gi[d]) * ftanh(Y0[512 + d] + Gi[512 + d])
                   + fl * cl + fr * cr;
    const float hv = fsig(Y0[256 + d] + Gi[256 + d]) * ftanh(cv);
    out[d] = cv;
    out[256 + d] = hv;
}

// ---------------------------------------------------------------------------
extern "C" void kernel_launch(void* const* d_in, const int* in_sizes, int n_in,
                              void* d_out, int out_size) {
    const float* X      = (const float*)d_in[0];
    const float* W_ioux = (const float*)d_in[1];
    const float* b_ioux = (const float*)d_in[2];
    const float* W_iouh = (const float*)d_in[3];
    const float* b_iouh = (const float*)d_in[4];
    const float* W_fx   = (const float*)d_in[5];
    const float* b_fx   = (const float*)d_in[6];
    const float* W_fh   = (const float*)d_in[7];
    const float* b_fh   = (const float*)d_in[8];
    float* out = (float*)d_out;

    cudaFuncSetAttribute(gemm_init_k,
                         cudaFuncAttributeMaxDynamicSharedMemorySize, SMEM_BYTES);
    cudaFuncSetAttribute(gemm_rec_k,
                         cudaFuncAttributeMaxDynamicSharedMemorySize, SMEM_BYTES);

    pack_weights_k<<<1024, 256>>>(W_ioux, b_ioux, W_iouh, b_iouh,
                                  W_fx, b_fx, W_fh, b_fh);
    convert_x_k<<<32768, 256>>>(X);

    // Y = X @ W1^T + b1 ; fx slab (cols 768..1023) only for internal rows
    gemm_init_k<<<dim3(1024, 6), 256, SMEM_BYTES>>>(0);
    gemm_init_k<<<dim3(512, 2), 256, SMEM_BYTES>>>(6);

    // leaves (level 16)
    leaf_k<<<8192, 256>>>();

    for (int lvl = 15; lvl >= 1; lvl--) {
        const int c = 1 << lvl;
        const int start = c - 1;
        const int cs = 2 * c - 1;
        const int tiles_f = (2 * c + 127) >> 7;
        const int tiles_i = (c + 127) >> 7;
        gemm_rec_k<<<tiles_f * 2 + tiles_i * 6, 256, SMEM_BYTES>>>(cs, start, c);
        const int npairs = c / 2;
        combine_k<<<(npairs + 3) / 4, 256>>>(start, cs, (1 << (lvl - 1)) - 1,
                                             npairs);
    }
    // level 0 (root)
    gemm_rec_k<<<8, 256, SMEM_BYTES>>>(1, 0, 1);
    root_k<<<1, 256>>>(out);
}